// round 11
// baseline (speedup 1.0000x reference)
#include <cuda_runtime.h>
#include <cstdint>
#include <cstddef>

#define NN 1024
#define DF 16
#define KC 16                          // A cols per chunk
#define NCHUNK (NN / KC)               // 64
#define DEPTH 6                        // per-warp ring slots (5 in flight)
#define ASTR 20                        // staged row stride in floats (80 B, ≡4 mod 32)
#define WBUF (16 * ASTR)               // 320 floats = 1280 B per slot

__global__ void __launch_bounds__(128, 7)
graph_loss_kernel(const float* __restrict__ A,
                  const float* __restrict__ F,
                  float* __restrict__ out) {
    __shared__ float sA[4 * DEPTH * WBUF];     // 30720 B
    __shared__ float red[4];

    const int tid  = threadIdx.x;
    const int lane = tid & 31;
    const int wid  = tid >> 5;                 // 0..3
    const int b    = blockIdx.x >> 4;
    const int tile = blockIdx.x & 15;          // 64-row tile within batch

    // This warp's 16 global rows
    const float* __restrict__ Aw =
        A + (size_t)b * NN * NN + (size_t)(tile * 64 + wid * 16) * NN;
    const float* __restrict__ Fb = F + (size_t)b * NN * DF;

    float* sW = sA + wid * (DEPTH * WBUF);
    const unsigned sWu = (unsigned)__cvta_generic_to_shared(sW);

    // ---- per-warp cp.async of chunk c (16 rows x 16 cols = 1 KB) into slot ----
    auto issueA = [&](int c, int slot) {
        if (c < NCHUNK) {
            const float* s0 = Aw + c * KC;
            const unsigned d0 = sWu + (unsigned)slot * (WBUF * 4);
            #pragma unroll
            for (int q = 0; q < 2; ++q) {
                int lin = q * 32 + lane;
                int row = lin >> 2, u = lin & 3;
                asm volatile("cp.async.cg.shared.global [%0], [%1], 16;"
                             :: "r"(d0 + (unsigned)(row * ASTR + u * 4) * 4),
                                "l"(s0 + (size_t)row * NN + u * 4));
            }
        }
        asm volatile("cp.async.commit_group;");
    };

    issueA(0, 0); issueA(1, 1); issueA(2, 2); issueA(3, 3); issueA(4, 4);

    // fragment accumulators: acc[0..3] = ntile0 (cols 0-7), acc[4..7] = ntile1
    float acc[8];
    #pragma unroll
    for (int k = 0; k < 8; ++k) acc[k] = 0.0f;
    float dlo = 0.0f, dhi = 0.0f, slo = 0.0f, shi = 0.0f;

    // A fragment base: local row = lane>>2 (and +8), col = lane&3
    const float* pA0 = sW + (lane >> 2) * ASTR + (lane & 3);
    // B fragment bases in global F: k = lane&3, n = lane>>2 (nt0) / +8 (nt1)
    const float* fB0 = Fb + (size_t)(lane & 3) * DF + (lane >> 2);
    const float* fB1 = fB0 + 8;

    int rs = 0;                                // read slot = c % 6
    #pragma unroll 1
    for (int c = 0; c < NCHUNK; ++c) {
        asm volatile("cp.async.wait_group 4;" ::: "memory");
        __syncwarp();
        int ws = rs + 5; if (ws >= DEPTH) ws -= DEPTH;   // (c+5) % 6 == (c-1) % 6
        issueA(c + 5, ws);                     // refill slot read at iter c-1

        const float* pa = pA0 + rs * WBUF;
        const float* fb0 = fB0 + (size_t)(c * KC) * DF;
        const float* fb1 = fB1 + (size_t)(c * KC) * DF;

        #pragma unroll
        for (int ks = 0; ks < 2; ++ks) {
            float a0 = pa[ks * 8];
            float a1 = pa[8 * ASTR + ks * 8];
            float a2 = pa[ks * 8 + 4];
            float a3 = pa[8 * ASTR + ks * 8 + 4];

            float b0x = __ldg(fb0 + (size_t)(ks * 8) * DF);
            float b0y = __ldg(fb0 + (size_t)(ks * 8 + 4) * DF);
            float b1x = __ldg(fb1 + (size_t)(ks * 8) * DF);
            float b1y = __ldg(fb1 + (size_t)(ks * 8 + 4) * DF);

            dlo += a0 + a2;  dhi += a1 + a3;
            slo = fmaf(a0, a0, fmaf(a2, a2, slo));
            shi = fmaf(a1, a1, fmaf(a3, a3, shi));

            unsigned ua0 = __float_as_uint(a0), ua1 = __float_as_uint(a1);
            unsigned ua2 = __float_as_uint(a2), ua3 = __float_as_uint(a3);

            asm volatile(
                "mma.sync.aligned.m16n8k8.row.col.f32.tf32.tf32.f32 "
                "{%0,%1,%2,%3}, {%4,%5,%6,%7}, {%8,%9}, {%0,%1,%2,%3};"
                : "+f"(acc[0]), "+f"(acc[1]), "+f"(acc[2]), "+f"(acc[3])
                : "r"(ua0), "r"(ua1), "r"(ua2), "r"(ua3),
                  "r"(__float_as_uint(b0x)), "r"(__float_as_uint(b0y)));
            asm volatile(
                "mma.sync.aligned.m16n8k8.row.col.f32.tf32.tf32.f32 "
                "{%0,%1,%2,%3}, {%4,%5,%6,%7}, {%8,%9}, {%0,%1,%2,%3};"
                : "+f"(acc[4]), "+f"(acc[5]), "+f"(acc[6]), "+f"(acc[7])
                : "r"(ua0), "r"(ua1), "r"(ua2), "r"(ua3),
                  "r"(__float_as_uint(b1x)), "r"(__float_as_uint(b1y)));
        }
        if (++rs >= DEPTH) rs = 0;
    }

    // ---- epilogue ----
    // Lane holds rows gr0 = tile*64 + 16*wid + lane/4 and gr1 = gr0+8;
    // D cols {2c,2c+1} (nt0) and {8+2c,9+2c} (nt1), c = lane&3.
    const int gr0 = tile * 64 + (wid << 4) + (lane >> 2);
    const int gr1 = gr0 + 8;
    const int c2  = (lane & 3) * 2;

    float2 f0a = *reinterpret_cast<const float2*>(Fb + (size_t)gr0 * DF + c2);
    float2 f0b = *reinterpret_cast<const float2*>(Fb + (size_t)gr0 * DF + 8 + c2);
    float2 f1a = *reinterpret_cast<const float2*>(Fb + (size_t)gr1 * DF + c2);
    float2 f1b = *reinterpret_cast<const float2*>(Fb + (size_t)gr1 * DF + 8 + c2);

    float t2lo = f0a.x * acc[0] + f0a.y * acc[1] + f0b.x * acc[4] + f0b.y * acc[5];
    float t2hi = f1a.x * acc[2] + f1a.y * acc[3] + f1b.x * acc[6] + f1b.y * acc[7];
    float t1lo = f0a.x * f0a.x + f0a.y * f0a.y + f0b.x * f0b.x + f0b.y * f0b.y;
    float t1hi = f1a.x * f1a.x + f1a.y * f1a.y + f1b.x * f1b.x + f1b.y * f1b.y;

    #pragma unroll
    for (int o = 1; o <= 2; o <<= 1) {
        t2lo += __shfl_xor_sync(0xffffffffu, t2lo, o);
        t2hi += __shfl_xor_sync(0xffffffffu, t2hi, o);
        t1lo += __shfl_xor_sync(0xffffffffu, t1lo, o);
        t1hi += __shfl_xor_sync(0xffffffffu, t1hi, o);
        dlo  += __shfl_xor_sync(0xffffffffu, dlo,  o);
        dhi  += __shfl_xor_sync(0xffffffffu, dhi,  o);
        slo  += __shfl_xor_sync(0xffffffffu, slo,  o);
        shi  += __shfl_xor_sync(0xffffffffu, shi,  o);
    }

    const float c1  = 0.2f / (1024.0f * 1024.0f);
    const float c2l = 0.1f / 1024.0f;
    const float c3  = 0.1f / (1024.0f * 1024.0f);

    float contrib = 0.0f;
    if ((lane & 3) == 0) {
        contrib = c1 * (dlo * t1lo - t2lo) - c2l * logf(dlo + 1e-12f) + c3 * slo
                + c1 * (dhi * t1hi - t2hi) - c2l * logf(dhi + 1e-12f) + c3 * shi;
    }
    #pragma unroll
    for (int o = 16; o; o >>= 1)
        contrib += __shfl_xor_sync(0xffffffffu, contrib, o);
    if (lane == 0) red[wid] = contrib;
    __syncthreads();
    if (tid == 0)
        atomicAdd(out + b, red[0] + red[1] + red[2] + red[3]);
}

extern "C" void kernel_launch(void* const* d_in, const int* in_sizes, int n_in,
                              void* d_out, int out_size) {
    const float* A = (const float*)d_in[0];   // out_adj [64,1024,1024]
    const float* F = (const float*)d_in[1];   // features [64,1024,16]
    float* out = (float*)d_out;               // [64]

    cudaMemsetAsync(out, 0, 64 * sizeof(float), 0);
    graph_loss_kernel<<<1024, 128>>>(A, F, out);
}

// round 12
// speedup vs baseline: 1.0663x; 1.0663x over previous
#include <cuda_runtime.h>
#include <cstdint>
#include <cstddef>

#define NN 1024
#define DF 16
#define KC 16                          // A cols per chunk
#define NCHUNK (NN / KC)               // 64
#define DEPTH 6                        // per-warp ring slots (5 in flight)
#define ASTR 20                        // staged row stride in floats (80 B, ≡4 mod 32)
#define WBUF (16 * ASTR)               // 320 floats = 1280 B per slot

// Precomputed B fragments: [b][c][ks][lane] -> (b0x, b0y, b1x, b1y). 4 MB.
__device__ float4 Btab[64 * NCHUNK * 2 * 32];

__global__ void build_btab_kernel(const float* __restrict__ F) {
    // blockIdx.x = b*NCHUNK + c ; tid = ks*32 + lane
    const int b    = blockIdx.x >> 6;
    const int c    = blockIdx.x & 63;
    const int ks   = threadIdx.x >> 5;
    const int lane = threadIdx.x & 31;
    const float* Fb = F + (size_t)b * NN * DF;
    const int r0 = c * KC + ks * 8 + (lane & 3);
    const int n0 = lane >> 2;
    float4 v;
    v.x = Fb[(size_t)r0 * DF + n0];
    v.y = Fb[(size_t)(r0 + 4) * DF + n0];
    v.z = Fb[(size_t)r0 * DF + n0 + 8];
    v.w = Fb[(size_t)(r0 + 4) * DF + n0 + 8];
    Btab[(size_t)blockIdx.x * 64 + threadIdx.x] = v;
}

__global__ void __launch_bounds__(128, 7)
graph_loss_kernel(const float* __restrict__ A,
                  const float* __restrict__ F,
                  float* __restrict__ out) {
    __shared__ float sA[4 * DEPTH * WBUF];     // 30720 B
    __shared__ float red[4];

    const int tid  = threadIdx.x;
    const int lane = tid & 31;
    const int wid  = tid >> 5;                 // 0..3
    const int b    = blockIdx.x >> 4;
    const int tile = blockIdx.x & 15;          // 64-row tile within batch

    // This warp's 16 global rows
    const float* __restrict__ Aw =
        A + (size_t)b * NN * NN + (size_t)(tile * 64 + wid * 16) * NN;
    const float* __restrict__ Fb = F + (size_t)b * NN * DF;

    float* sW = sA + wid * (DEPTH * WBUF);
    const unsigned sWu = (unsigned)__cvta_generic_to_shared(sW);

    // ---- per-warp cp.async of chunk c (16 rows x 16 cols = 1 KB) into slot ----
    auto issueA = [&](int c, int slot) {
        if (c < NCHUNK) {
            const float* s0 = Aw + c * KC;
            const unsigned d0 = sWu + (unsigned)slot * (WBUF * 4);
            #pragma unroll
            for (int q = 0; q < 2; ++q) {
                int lin = q * 32 + lane;
                int row = lin >> 2, u = lin & 3;
                asm volatile("cp.async.cg.shared.global [%0], [%1], 16;"
                             :: "r"(d0 + (unsigned)(row * ASTR + u * 4) * 4),
                                "l"(s0 + (size_t)row * NN + u * 4));
            }
        }
        asm volatile("cp.async.commit_group;");
    };

    issueA(0, 0); issueA(1, 1); issueA(2, 2); issueA(3, 3); issueA(4, 4);

    // fragment accumulators: acc[0..3] = ntile0 (cols 0-7), acc[4..7] = ntile1
    float acc[8];
    #pragma unroll
    for (int k = 0; k < 8; ++k) acc[k] = 0.0f;
    float dlo = 0.0f, dhi = 0.0f, slo = 0.0f, shi = 0.0f;

    // A fragment base: local row = lane>>2 (and +8), col = lane&3
    const float* pA0 = sW + (lane >> 2) * ASTR + (lane & 3);
    // B fragment table pointer for this batch: advances 64 float4 per chunk
    const float4* __restrict__ bt = Btab + ((size_t)b * NCHUNK) * 64 + lane;

    int rs = 0;                                // read slot = c % DEPTH
    #pragma unroll 1
    for (int c = 0; c < NCHUNK; ++c) {
        asm volatile("cp.async.wait_group 4;" ::: "memory");
        __syncwarp();
        int ws = rs + 5; if (ws >= DEPTH) ws -= DEPTH;
        issueA(c + 5, ws);                     // refill slot read at iter c-1

        const float* pa = pA0 + rs * WBUF;
        float4 bb0 = __ldg(bt);                // ks = 0 fragments
        float4 bb1 = __ldg(bt + 32);           // ks = 1 fragments
        bt += 64;

        #pragma unroll
        for (int ks = 0; ks < 2; ++ks) {
            float a0 = pa[ks * 8];
            float a1 = pa[8 * ASTR + ks * 8];
            float a2 = pa[ks * 8 + 4];
            float a3 = pa[8 * ASTR + ks * 8 + 4];

            const float4 bb = ks ? bb1 : bb0;

            dlo += a0 + a2;  dhi += a1 + a3;
            slo = fmaf(a0, a0, fmaf(a2, a2, slo));
            shi = fmaf(a1, a1, fmaf(a3, a3, shi));

            unsigned ua0 = __float_as_uint(a0), ua1 = __float_as_uint(a1);
            unsigned ua2 = __float_as_uint(a2), ua3 = __float_as_uint(a3);

            asm volatile(
                "mma.sync.aligned.m16n8k8.row.col.f32.tf32.tf32.f32 "
                "{%0,%1,%2,%3}, {%4,%5,%6,%7}, {%8,%9}, {%0,%1,%2,%3};"
                : "+f"(acc[0]), "+f"(acc[1]), "+f"(acc[2]), "+f"(acc[3])
                : "r"(ua0), "r"(ua1), "r"(ua2), "r"(ua3),
                  "r"(__float_as_uint(bb.x)), "r"(__float_as_uint(bb.y)));
            asm volatile(
                "mma.sync.aligned.m16n8k8.row.col.f32.tf32.tf32.f32 "
                "{%0,%1,%2,%3}, {%4,%5,%6,%7}, {%8,%9}, {%0,%1,%2,%3};"
                : "+f"(acc[4]), "+f"(acc[5]), "+f"(acc[6]), "+f"(acc[7])
                : "r"(ua0), "r"(ua1), "r"(ua2), "r"(ua3),
                  "r"(__float_as_uint(bb.z)), "r"(__float_as_uint(bb.w)));
        }
        if (++rs >= DEPTH) rs = 0;
    }

    // ---- epilogue ----
    // Lane holds rows gr0 = tile*64 + 16*wid + lane/4 and gr1 = gr0+8;
    // D cols {2c,2c+1} (nt0) and {8+2c,9+2c} (nt1), c = lane&3.
    const int gr0 = tile * 64 + (wid << 4) + (lane >> 2);
    const int gr1 = gr0 + 8;
    const int c2  = (lane & 3) * 2;

    float2 f0a = *reinterpret_cast<const float2*>(Fb + (size_t)gr0 * DF + c2);
    float2 f0b = *reinterpret_cast<const float2*>(Fb + (size_t)gr0 * DF + 8 + c2);
    float2 f1a = *reinterpret_cast<const float2*>(Fb + (size_t)gr1 * DF + c2);
    float2 f1b = *reinterpret_cast<const float2*>(Fb + (size_t)gr1 * DF + 8 + c2);

    float t2lo = f0a.x * acc[0] + f0a.y * acc[1] + f0b.x * acc[4] + f0b.y * acc[5];
    float t2hi = f1a.x * acc[2] + f1a.y * acc[3] + f1b.x * acc[6] + f1b.y * acc[7];
    float t1lo = f0a.x * f0a.x + f0a.y * f0a.y + f0b.x * f0b.x + f0b.y * f0b.y;
    float t1hi = f1a.x * f1a.x + f1a.y * f1a.y + f1b.x * f1b.x + f1b.y * f1b.y;

    #pragma unroll
    for (int o = 1; o <= 2; o <<= 1) {
        t2lo += __shfl_xor_sync(0xffffffffu, t2lo, o);
        t2hi += __shfl_xor_sync(0xffffffffu, t2hi, o);
        t1lo += __shfl_xor_sync(0xffffffffu, t1lo, o);
        t1hi += __shfl_xor_sync(0xffffffffu, t1hi, o);
        dlo  += __shfl_xor_sync(0xffffffffu, dlo,  o);
        dhi  += __shfl_xor_sync(0xffffffffu, dhi,  o);
        slo  += __shfl_xor_sync(0xffffffffu, slo,  o);
        shi  += __shfl_xor_sync(0xffffffffu, shi,  o);
    }

    const float c1  = 0.2f / (1024.0f * 1024.0f);
    const float c2l = 0.1f / 1024.0f;
    const float c3  = 0.1f / (1024.0f * 1024.0f);

    float contrib = 0.0f;
    if ((lane & 3) == 0) {
        contrib = c1 * (dlo * t1lo - t2lo) - c2l * logf(dlo + 1e-12f) + c3 * slo
                + c1 * (dhi * t1hi - t2hi) - c2l * logf(dhi + 1e-12f) + c3 * shi;
    }
    #pragma unroll
    for (int o = 16; o; o >>= 1)
        contrib += __shfl_xor_sync(0xffffffffu, contrib, o);
    if (lane == 0) red[wid] = contrib;
    __syncthreads();
    if (tid == 0)
        atomicAdd(out + b, red[0] + red[1] + red[2] + red[3]);
}

extern "C" void kernel_launch(void* const* d_in, const int* in_sizes, int n_in,
                              void* d_out, int out_size) {
    const float* A = (const float*)d_in[0];   // out_adj [64,1024,1024]
    const float* F = (const float*)d_in[1];   // features [64,1024,16]
    float* out = (float*)d_out;               // [64]

    cudaMemsetAsync(out, 0, 64 * sizeof(float), 0);
    build_btab_kernel<<<64 * NCHUNK, 64>>>(F);
    graph_loss_kernel<<<1024, 128>>>(A, F, out);
}